// round 1
// baseline (speedup 1.0000x reference)
#include <cuda_runtime.h>
#include <cuda_bf16.h>
#include <math.h>

// ---------------------------------------------------------------------------
// DeformableCrossAttention, restructured:
//   Wkv  = Wk @ Wv                         (512x512)
//   Wqo  = Wq @ Woff                       (512x64)
//   Wqa  = Wq @ Watt                       (512x32)
//   Wow  = Wo @ Wout                       (512x512)
//   bow  = bo @ Wout + bout                (512)
//   value = context @ Wkv + bv             [32768, 512]
//   loff  = x @ Wqo + boff                 [32768, 64]
//   latt  = x @ Wqa + batt                 [32768, 32]
//   mid   = deform_sample(value, loff, latt)  [32768, 512]
//   out   = mid @ Wow + bow                [32768, 512]
// Shapes fixed by the dataset: bs=8, H=W=64, wh=4096, M=8 heads, D=64, P=4.
// ---------------------------------------------------------------------------

#define BS     8
#define Hh     64
#define Ww     64
#define WH     4096
#define ROWS   (BS * WH)       // 32768
#define CH     512
#define NHEAD  8
#define DHEAD  64
#define NPTS   4

// ------------------------- scratch (device globals) ------------------------
__device__ float g_Wkv[CH * CH];
__device__ float g_Wow[CH * CH];
__device__ float g_Wqo[CH * 64];
__device__ float g_Wqa[CH * 32];
__device__ float g_bow[CH];
__device__ float g_value[(size_t)ROWS * CH];
__device__ float g_loff[(size_t)ROWS * 64];
__device__ float g_latt[(size_t)ROWS * 32];
__device__ float g_mid[(size_t)ROWS * CH];

// ------------------------------ SGEMM --------------------------------------
// C[M,N] = A[M,K] @ B[K,N] (+ bias[N]); row-major; M%128==0, K%16==0, N%4==0.
#define BM 128
#define BN 128
#define BK 16
#define TM 8
#define TN 8

__global__ __launch_bounds__(256) void sgemm_bias(
    const float* __restrict__ A, const float* __restrict__ B,
    const float* __restrict__ bias, float* __restrict__ C,
    int M, int N, int K)
{
    __shared__ float As[BK][BM];
    __shared__ float Bs[BK][BN];

    const int tid  = threadIdx.x;
    const int row0 = blockIdx.y * BM;
    const int col0 = blockIdx.x * BN;
    const int tx   = tid & 15;   // 0..15 (N dir)
    const int ty   = tid >> 4;   // 0..15 (M dir)

    // A-tile loader: 128 rows x 16 cols = 512 float4; 2 per thread
    const int aRow  = tid >> 2;          // 0..63
    const int aCol4 = (tid & 3) << 2;    // 0,4,8,12
    // B-tile loader: 16 rows x 128 cols = 512 float4; 2 per thread
    const int bRow  = tid >> 5;          // 0..7
    const int bCol4 = (tid & 31) << 2;   // 0..124

    float acc[TM][TN];
#pragma unroll
    for (int i = 0; i < TM; i++)
#pragma unroll
        for (int j = 0; j < TN; j++) acc[i][j] = 0.f;

    for (int k0 = 0; k0 < K; k0 += BK) {
#pragma unroll
        for (int it = 0; it < 2; it++) {
            int r = aRow + it * 64;
            float4 v = *reinterpret_cast<const float4*>(
                A + (size_t)(row0 + r) * K + k0 + aCol4);
            As[aCol4 + 0][r] = v.x;
            As[aCol4 + 1][r] = v.y;
            As[aCol4 + 2][r] = v.z;
            As[aCol4 + 3][r] = v.w;
        }
#pragma unroll
        for (int it = 0; it < 2; it++) {
            int r    = bRow + it * 8;
            int gcol = col0 + bCol4;
            float4 v = make_float4(0.f, 0.f, 0.f, 0.f);
            if (gcol < N)
                v = *reinterpret_cast<const float4*>(
                    B + (size_t)(k0 + r) * N + gcol);
            *reinterpret_cast<float4*>(&Bs[r][bCol4]) = v;
        }
        __syncthreads();

#pragma unroll
        for (int k = 0; k < BK; k++) {
            float a[TM], b[TN];
#pragma unroll
            for (int i = 0; i < TM; i++) a[i] = As[k][ty * TM + i];
#pragma unroll
            for (int j = 0; j < TN; j++) b[j] = Bs[k][tx * TN + j];
#pragma unroll
            for (int i = 0; i < TM; i++)
#pragma unroll
                for (int j = 0; j < TN; j++) acc[i][j] = fmaf(a[i], b[j], acc[i][j]);
        }
        __syncthreads();
    }

    // epilogue
    float bv8[TN];
#pragma unroll
    for (int j = 0; j < TN; j++) {
        int c = col0 + tx * TN + j;
        bv8[j] = (bias && c < N) ? bias[c] : 0.f;
    }
    if (col0 + BN <= N) {
#pragma unroll
        for (int i = 0; i < TM; i++) {
            float* crow = C + (size_t)(row0 + ty * TM + i) * N + col0 + tx * TN;
            float4 v0 = make_float4(acc[i][0] + bv8[0], acc[i][1] + bv8[1],
                                    acc[i][2] + bv8[2], acc[i][3] + bv8[3]);
            float4 v1 = make_float4(acc[i][4] + bv8[4], acc[i][5] + bv8[5],
                                    acc[i][6] + bv8[6], acc[i][7] + bv8[7]);
            *reinterpret_cast<float4*>(crow)     = v0;
            *reinterpret_cast<float4*>(crow + 4) = v1;
        }
    } else {
#pragma unroll
        for (int i = 0; i < TM; i++)
#pragma unroll
            for (int j = 0; j < TN; j++) {
                int c = col0 + tx * TN + j;
                if (c < N)
                    C[(size_t)(row0 + ty * TM + i) * N + c] = acc[i][j] + bv8[j];
            }
    }
}

// --------------------------- bias fold: bow --------------------------------
__global__ void fold_bias(const float* __restrict__ bo,
                          const float* __restrict__ Wout,
                          const float* __restrict__ bout)
{
    int j = blockIdx.x * blockDim.x + threadIdx.x;
    if (j >= CH) return;
    float s = bout[j];
    for (int k = 0; k < CH; k++) s = fmaf(bo[k], Wout[k * CH + j], s);
    g_bow[j] = s;
}

// ------------------- fused softmax + bilinear sampling ---------------------
// One warp per (b, pos, m). Lane l handles channels 2l and 2l+1 (float2).
__global__ __launch_bounds__(256) void deform_sample(
    const float* __restrict__ value,   // [ROWS, 512]  (b*4096+pos rows)
    const float* __restrict__ loff,    // [ROWS, 64]
    const float* __restrict__ latt,    // [ROWS, 32]
    float* __restrict__ outm)          // [ROWS, 512]
{
    int warp = (blockIdx.x * blockDim.x + threadIdx.x) >> 5;
    int lane = threadIdx.x & 31;
    if (warp >= ROWS * NHEAD) return;

    int m  = warp & 7;
    int bq = warp >> 3;          // b*4096 + pos
    int b  = bq >> 12;
    int pos = bq & 4095;
    float col = (float)(pos & 63);
    float row = (float)(pos >> 6);

    const float* lo = loff + (size_t)bq * 64 + m * 8;
    const float* la = latt + (size_t)bq * 32 + m * 4;

    // softmax over the 4 points
    float l0 = la[0], l1 = la[1], l2 = la[2], l3 = la[3];
    float mx = fmaxf(fmaxf(l0, l1), fmaxf(l2, l3));
    float e0 = __expf(l0 - mx), e1 = __expf(l1 - mx),
          e2 = __expf(l2 - mx), e3 = __expf(l3 - mx);
    float inv = 1.f / (e0 + e1 + e2 + e3);
    float aw[4] = {e0 * inv, e1 * inv, e2 * inv, e3 * inv};

    const float* vbase = value + ((size_t)b * WH) * CH + m * DHEAD + 2 * lane;
    float accx = 0.f, accy = 0.f;

#pragma unroll
    for (int p = 0; p < NPTS; p++) {
        // pixel coords simplify exactly to (col + off_x, row + off_y)
        float x = col + lo[2 * p];
        float y = row + lo[2 * p + 1];
        float xf = floorf(x), yf = floorf(y);
        float wx1 = x - xf, wy1 = y - yf;
        int x0 = (int)xf, y0 = (int)yf;
        float a = aw[p];
#pragma unroll
        for (int dy = 0; dy < 2; dy++) {
#pragma unroll
            for (int dx = 0; dx < 2; dx++) {
                int xi = x0 + dx, yi = y0 + dy;
                if ((unsigned)xi < 64u && (unsigned)yi < 64u) {
                    float w = a * (dx ? wx1 : 1.f - wx1) * (dy ? wy1 : 1.f - wy1);
                    float2 v = *reinterpret_cast<const float2*>(
                        vbase + (size_t)(yi * 64 + xi) * CH);
                    accx = fmaf(w, v.x, accx);
                    accy = fmaf(w, v.y, accy);
                }
            }
        }
    }
    float2 o = make_float2(accx, accy);
    *reinterpret_cast<float2*>(outm + (size_t)bq * CH + m * DHEAD + 2 * lane) = o;
}

// ------------------------------- launch ------------------------------------
extern "C" void kernel_launch(void* const* d_in, const int* in_sizes, int n_in,
                              void* d_out, int out_size)
{
    const float* x    = (const float*)d_in[0];
    const float* ctx  = (const float*)d_in[1];
    // d_in[2], d_in[3]: spatial shapes (static 64x64, unused)
    const float* Wq   = (const float*)d_in[4];
    const float* Wk   = (const float*)d_in[5];
    const float* Wv   = (const float*)d_in[6];
    const float* bv   = (const float*)d_in[7];
    const float* Woff = (const float*)d_in[8];
    const float* boff = (const float*)d_in[9];
    const float* Watt = (const float*)d_in[10];
    const float* batt = (const float*)d_in[11];
    const float* Wo   = (const float*)d_in[12];
    const float* bo   = (const float*)d_in[13];
    const float* Wout = (const float*)d_in[14];
    const float* bout = (const float*)d_in[15];
    float* out = (float*)d_out;

    static float *p_Wkv = nullptr, *p_Wow = nullptr, *p_Wqo = nullptr,
                 *p_Wqa = nullptr, *p_bow = nullptr, *p_value = nullptr,
                 *p_loff = nullptr, *p_latt = nullptr, *p_mid = nullptr;
    if (!p_Wkv) {
        cudaGetSymbolAddress((void**)&p_Wkv, g_Wkv);
        cudaGetSymbolAddress((void**)&p_Wow, g_Wow);
        cudaGetSymbolAddress((void**)&p_Wqo, g_Wqo);
        cudaGetSymbolAddress((void**)&p_Wqa, g_Wqa);
        cudaGetSymbolAddress((void**)&p_bow, g_bow);
        cudaGetSymbolAddress((void**)&p_value, g_value);
        cudaGetSymbolAddress((void**)&p_loff, g_loff);
        cudaGetSymbolAddress((void**)&p_latt, g_latt);
        cudaGetSymbolAddress((void**)&p_mid, g_mid);
    }

    dim3 blk(256);

    // weight folds (tiny GEMMs)
    sgemm_bias<<<dim3(4, 4), blk>>>(Wk, Wv, nullptr, p_Wkv, CH, CH, CH);
    sgemm_bias<<<dim3(4, 4), blk>>>(Wo, Wout, nullptr, p_Wow, CH, CH, CH);
    sgemm_bias<<<dim3(1, 4), blk>>>(Wq, Woff, nullptr, p_Wqo, CH, 64, CH);
    sgemm_bias<<<dim3(1, 4), blk>>>(Wq, Watt, nullptr, p_Wqa, CH, 32, CH);
    fold_bias<<<1, 512>>>(bo, Wout, bout);

    // main projections
    sgemm_bias<<<dim3(4, 256), blk>>>(ctx, p_Wkv, bv, p_value, ROWS, CH, CH);
    sgemm_bias<<<dim3(1, 256), blk>>>(x, p_Wqo, boff, p_loff, ROWS, 64, CH);
    sgemm_bias<<<dim3(1, 256), blk>>>(x, p_Wqa, batt, p_latt, ROWS, 32, CH);

    // fused softmax + deformable bilinear sampling
    int nwarps = ROWS * NHEAD;                 // 262144
    deform_sample<<<(nwarps * 32 + 255) / 256, blk>>>(p_value, p_loff, p_latt, p_mid);

    // output projection (folded Wo@Wout)
    sgemm_bias<<<dim3(4, 256), blk>>>(p_mid, p_Wow, p_bow, out, ROWS, CH, CH);
}

// round 2
// speedup vs baseline: 2.1303x; 2.1303x over previous
#include <cuda_runtime.h>
#include <cuda_bf16.h>
#include <math.h>

// ---------------------------------------------------------------------------
// DeformableCrossAttention, restructured (all GEMMs on tensor pipe, tf32):
//   Wkv  = Wk @ Wv                          (512x512)
//   Wow  = Wo @ Wout, bow = bo@Wout + bout  (512x512)
//   Wcomb = [Wq@Woff | Wq@Watt]             (512x96)
//   value  = context @ Wkv + bv             [32768, 512]
//   la     = x @ Wcomb + [boff|batt]        [32768, 96]
//   mid    = deform_sample(value, la)       [32768, 512]
//   out    = mid @ Wow + bow                [32768, 512]
// bs=8, H=W=64, wh=4096, M=8 heads, D=64, P=4.
// ---------------------------------------------------------------------------

#define BS     8
#define WH     4096
#define ROWS   (BS * WH)       // 32768
#define CH     512
#define NHEAD  8
#define DHEAD  64
#define NPTS   4
#define NLA    96              // 64 offsets + 32 attn logits

// ------------------------- scratch (device globals) ------------------------
__device__ float g_Wkv[CH * CH];
__device__ float g_Wow[CH * CH];
__device__ float g_Wcomb[CH * NLA];
__device__ float g_bcomb[NLA];
__device__ float g_bow[CH];
__device__ float g_value[(size_t)ROWS * CH];
__device__ float g_la[(size_t)ROWS * NLA];
__device__ float g_mid[(size_t)ROWS * CH];

// --------------------------- tf32 helpers ----------------------------------
__device__ __forceinline__ float f2tf32(float f) {
    unsigned r;
    asm("cvt.rna.tf32.f32 %0, %1;" : "=r"(r) : "f"(f));
    return __uint_as_float(r);
}

// ------------------------- tf32 tensor GEMM --------------------------------
// C[M,N] = A[M,K] @ B[K,N] (+bias); A row stride K, B row stride ldb,
// C row stride ldc. M%128==0, K%16==0, N%8==0.
// Block: 256 thr = 8 warps (2x4), tile 128x128, warp tile 64x32, BK=16.
#define TBK 16
#define AS_LD 20    // 16+4: frag banks (20*qr+qc) all distinct, float4-aligned
#define BS_LD 136   // 128+8: frag banks (8*qc+qr) all distinct

__global__ __launch_bounds__(256) void tgemm(
    const float* __restrict__ A, const float* __restrict__ B,
    const float* __restrict__ bias, float* __restrict__ C,
    int M, int N, int K, int ldb, int ldc)
{
    __shared__ float As[128][AS_LD];
    __shared__ float Bsm[TBK][BS_LD];

    const int tid  = threadIdx.x;
    const int row0 = blockIdx.y * 128;
    const int col0 = blockIdx.x * 128;
    const int wid  = tid >> 5;
    const int lane = tid & 31;
    const int warpM = (wid & 1) * 64;
    const int warpN = (wid >> 1) * 32;
    const int qr = lane >> 2;   // 0..7
    const int qc = lane & 3;    // 0..3

    float acc[4][4][4];
#pragma unroll
    for (int mt = 0; mt < 4; mt++)
#pragma unroll
        for (int nt = 0; nt < 4; nt++)
#pragma unroll
            for (int i = 0; i < 4; i++) acc[mt][nt][i] = 0.f;

    for (int k0 = 0; k0 < K; k0 += TBK) {
        // A tile: 128x16 = 512 float4, 2 per thread
#pragma unroll
        for (int it = 0; it < 2; it++) {
            int idx = tid + it * 256;
            int r = idx >> 2, c4 = (idx & 3) << 2;
            float4 v = *reinterpret_cast<const float4*>(
                A + (size_t)(row0 + r) * K + k0 + c4);
            As[r][c4 + 0] = f2tf32(v.x);
            As[r][c4 + 1] = f2tf32(v.y);
            As[r][c4 + 2] = f2tf32(v.z);
            As[r][c4 + 3] = f2tf32(v.w);
        }
        // B tile: 16x128 = 512 float4, 2 per thread
#pragma unroll
        for (int it = 0; it < 2; it++) {
            int idx = tid + it * 256;
            int r = idx >> 5, c4 = (idx & 31) << 2;
            int gc = col0 + c4;
            float4 v = make_float4(0.f, 0.f, 0.f, 0.f);
            if (gc + 3 < N)
                v = *reinterpret_cast<const float4*>(
                    B + (size_t)(k0 + r) * ldb + gc);
            Bsm[r][c4 + 0] = f2tf32(v.x);
            Bsm[r][c4 + 1] = f2tf32(v.y);
            Bsm[r][c4 + 2] = f2tf32(v.z);
            Bsm[r][c4 + 3] = f2tf32(v.w);
        }
        __syncthreads();

#pragma unroll
        for (int ks = 0; ks < 2; ks++) {
            const int kb = ks * 8;
            // B fragments: b[nt][0..1]
            unsigned bfr[4][2];
#pragma unroll
            for (int nt = 0; nt < 4; nt++) {
                int bc = warpN + nt * 8 + qr;
                bfr[nt][0] = __float_as_uint(Bsm[kb + qc][bc]);
                bfr[nt][1] = __float_as_uint(Bsm[kb + qc + 4][bc]);
            }
#pragma unroll
            for (int mt = 0; mt < 4; mt++) {
                int ar = warpM + mt * 16 + qr;
                unsigned a0 = __float_as_uint(As[ar][kb + qc]);
                unsigned a1 = __float_as_uint(As[ar + 8][kb + qc]);
                unsigned a2 = __float_as_uint(As[ar][kb + qc + 4]);
                unsigned a3 = __float_as_uint(As[ar + 8][kb + qc + 4]);
#pragma unroll
                for (int nt = 0; nt < 4; nt++) {
                    asm volatile(
                        "mma.sync.aligned.m16n8k8.row.col.f32.tf32.tf32.f32 "
                        "{%0,%1,%2,%3}, {%4,%5,%6,%7}, {%8,%9}, {%0,%1,%2,%3};\n"
                        : "+f"(acc[mt][nt][0]), "+f"(acc[mt][nt][1]),
                          "+f"(acc[mt][nt][2]), "+f"(acc[mt][nt][3])
                        : "r"(a0), "r"(a1), "r"(a2), "r"(a3),
                          "r"(bfr[nt][0]), "r"(bfr[nt][1]));
                }
            }
        }
        __syncthreads();
    }

    // epilogue: c0:(r, 2qc) c1:(r, 2qc+1) c2:(r+8, 2qc) c3:(r+8, 2qc+1)
#pragma unroll
    for (int nt = 0; nt < 4; nt++) {
        int col = col0 + warpN + nt * 8 + qc * 2;
        if (col >= N) continue;
        float b0 = bias ? bias[col] : 0.f;
        float b1 = bias ? bias[col + 1] : 0.f;
#pragma unroll
        for (int mt = 0; mt < 4; mt++) {
            int row = row0 + warpM + mt * 16 + qr;
            float2 v0 = make_float2(acc[mt][nt][0] + b0, acc[mt][nt][1] + b1);
            float2 v1 = make_float2(acc[mt][nt][2] + b0, acc[mt][nt][3] + b1);
            *reinterpret_cast<float2*>(C + (size_t)row * ldc + col) = v0;
            *reinterpret_cast<float2*>(C + (size_t)(row + 8) * ldc + col) = v1;
        }
    }
}

// --------------------------- bias folds ------------------------------------
__global__ void fold_bias(const float* __restrict__ bo,
                          const float* __restrict__ Wout,
                          const float* __restrict__ bout,
                          const float* __restrict__ boff,
                          const float* __restrict__ batt)
{
    int j = blockIdx.x * blockDim.x + threadIdx.x;
    if (j < CH) {
        float s = bout[j];
        for (int k = 0; k < CH; k++) s = fmaf(bo[k], Wout[k * CH + j], s);
        g_bow[j] = s;
    }
    if (j < 64)  g_bcomb[j] = boff[j];
    else if (j < NLA) g_bcomb[j] = batt[j - 64];
}

// ------------------- fused softmax + bilinear sampling ---------------------
// One warp per (b, pos, m). Lane l handles channels 2l, 2l+1.
__global__ __launch_bounds__(256) void deform_sample(
    const float* __restrict__ value,   // [ROWS, 512]
    const float* __restrict__ la,      // [ROWS, 96]: 64 off + 32 att
    float* __restrict__ outm)          // [ROWS, 512]
{
    int warp = (blockIdx.x * blockDim.x + threadIdx.x) >> 5;
    int lane = threadIdx.x & 31;
    if (warp >= ROWS * NHEAD) return;

    int m   = warp & 7;
    int bq  = warp >> 3;
    int b   = bq >> 12;
    int pos = bq & 4095;
    float col = (float)(pos & 63);
    float row = (float)(pos >> 6);

    const float* lo  = la + (size_t)bq * NLA + m * 8;
    const float* lat = la + (size_t)bq * NLA + 64 + m * 4;

    float l0 = lat[0], l1 = lat[1], l2 = lat[2], l3 = lat[3];
    float mx = fmaxf(fmaxf(l0, l1), fmaxf(l2, l3));
    float e0 = __expf(l0 - mx), e1 = __expf(l1 - mx),
          e2 = __expf(l2 - mx), e3 = __expf(l3 - mx);
    float inv = 1.f / (e0 + e1 + e2 + e3);
    float aw[4] = {e0 * inv, e1 * inv, e2 * inv, e3 * inv};

    const float* vbase = value + ((size_t)b * WH) * CH + m * DHEAD + 2 * lane;
    float accx = 0.f, accy = 0.f;

#pragma unroll
    for (int p = 0; p < NPTS; p++) {
        float x = col + lo[2 * p];
        float y = row + lo[2 * p + 1];
        float xf = floorf(x), yf = floorf(y);
        float wx1 = x - xf, wy1 = y - yf;
        int x0 = (int)xf, y0 = (int)yf;
        float a = aw[p];
#pragma unroll
        for (int dy = 0; dy < 2; dy++) {
#pragma unroll
            for (int dx = 0; dx < 2; dx++) {
                int xi = x0 + dx, yi = y0 + dy;
                if ((unsigned)xi < 64u && (unsigned)yi < 64u) {
                    float w = a * (dx ? wx1 : 1.f - wx1) * (dy ? wy1 : 1.f - wy1);
                    float2 v = *reinterpret_cast<const float2*>(
                        vbase + (size_t)(yi * 64 + xi) * CH);
                    accx = fmaf(w, v.x, accx);
                    accy = fmaf(w, v.y, accy);
                }
            }
        }
    }
    *reinterpret_cast<float2*>(outm + (size_t)bq * CH + m * DHEAD + 2 * lane) =
        make_float2(accx, accy);
}

// ------------------------------- launch ------------------------------------
extern "C" void kernel_launch(void* const* d_in, const int* in_sizes, int n_in,
                              void* d_out, int out_size)
{
    const float* x    = (const float*)d_in[0];
    const float* ctx  = (const float*)d_in[1];
    const float* Wq   = (const float*)d_in[4];
    const float* Wk   = (const float*)d_in[5];
    const float* Wv   = (const float*)d_in[6];
    const float* bv   = (const float*)d_in[7];
    const float* Woff = (const float*)d_in[8];
    const float* boff = (const float*)d_in[9];
    const float* Watt = (const float*)d_in[10];
    const float* batt = (const float*)d_in[11];
    const float* Wo   = (const float*)d_in[12];
    const float* bo   = (const float*)d_in[13];
    const float* Wout = (const float*)d_in[14];
    const float* bout = (const float*)d_in[15];
    float* out = (float*)d_out;

    static float *p_Wkv = nullptr, *p_Wow = nullptr, *p_Wcomb = nullptr,
                 *p_bcomb = nullptr, *p_bow = nullptr, *p_value = nullptr,
                 *p_la = nullptr, *p_mid = nullptr;
    if (!p_Wkv) {
        cudaGetSymbolAddress((void**)&p_Wkv, g_Wkv);
        cudaGetSymbolAddress((void**)&p_Wow, g_Wow);
        cudaGetSymbolAddress((void**)&p_Wcomb, g_Wcomb);
        cudaGetSymbolAddress((void**)&p_bcomb, g_bcomb);
        cudaGetSymbolAddress((void**)&p_bow, g_bow);
        cudaGetSymbolAddress((void**)&p_value, g_value);
        cudaGetSymbolAddress((void**)&p_la, g_la);
        cudaGetSymbolAddress((void**)&p_mid, g_mid);
    }

    dim3 blk(256);

    // weight folds (tf32 tensor)
    tgemm<<<dim3(4, 4), blk>>>(Wk, Wv, nullptr, p_Wkv, CH, CH, CH, CH, CH);
    tgemm<<<dim3(4, 4), blk>>>(Wo, Wout, nullptr, p_Wow, CH, CH, CH, CH, CH);
    tgemm<<<dim3(1, 4), blk>>>(Wq, Woff, nullptr, p_Wcomb, CH, 64, CH, 64, NLA);
    tgemm<<<dim3(1, 4), blk>>>(Wq, Watt, nullptr, p_Wcomb + 64, CH, 32, CH, 32, NLA);
    fold_bias<<<1, 512>>>(bo, Wout, bout, boff, batt);

    // main projections
    tgemm<<<dim3(4, 256), blk>>>(ctx, p_Wkv, bv, p_value, ROWS, CH, CH, CH, CH);
    tgemm<<<dim3(1, 256), blk>>>(x, p_Wcomb, p_bcomb, p_la, ROWS, NLA, CH, NLA, NLA);

    // fused softmax + deformable bilinear sampling
    int nwarps = ROWS * NHEAD;
    deform_sample<<<(nwarps * 32 + 255) / 256, blk>>>(p_value, p_la, p_mid);

    // output projection (folded Wo@Wout)
    tgemm<<<dim3(4, 256), blk>>>(p_mid, p_Wow, p_bow, out, ROWS, CH, CH, CH, CH);
}

// round 3
// speedup vs baseline: 3.2612x; 1.5308x over previous
#include <cuda_runtime.h>
#include <cuda_bf16.h>
#include <math.h>

// ---------------------------------------------------------------------------
// DeformableCrossAttention, restructured (all GEMMs tf32 tensor-pipe):
//   fold_all (1 launch):
//     Wkv  = Wk @ Wv        Wow = Wo @ Wout
//     Wcomb = [Wq@Woff | Wq@Watt]
//   value  = context @ Wkv + bv             [32768, 512]
//   la     = x @ Wcomb + [boff|batt]        [32768, 96]
//   mid    = deform_sample(value, la)       [32768, 512]
//   out    = mid @ Wow + (bo@Wout + bout)   [32768, 512]
// bs=8, H=W=64, wh=4096, M=8 heads, D=64, P=4.
// ---------------------------------------------------------------------------

#define BS     8
#define WH     4096
#define ROWS   (BS * WH)       // 32768
#define CH     512
#define NHEAD  8
#define DHEAD  64
#define NPTS   4
#define NLA    96              // 64 offsets + 32 attn logits

// ------------------------- scratch (device globals) ------------------------
__device__ float g_Wkv[CH * CH];
__device__ float g_Wow[CH * CH];
__device__ float g_Wcomb[CH * NLA];
__device__ float g_bcomb[NLA];
__device__ float g_bow[CH];
__device__ float g_value[(size_t)ROWS * CH];
__device__ float g_la[(size_t)ROWS * NLA];
__device__ float g_mid[(size_t)ROWS * CH];

// --------------------------- tf32 helpers ----------------------------------
__device__ __forceinline__ float f2tf32(float f) {
    unsigned r;
    asm("cvt.rna.tf32.f32 %0, %1;" : "=r"(r) : "f"(f));
    return __uint_as_float(r);
}

// ------------------------- tf32 tensor GEMM body ---------------------------
// C[M,N] = A[M,K] @ B[K,N] (+bias); double-buffered smem, register prefetch.
// Block 256 thr = 8 warps (2x4), tile 128x128, warp tile 64x32, BK=16.
#define TBK 16
#define AS_LD 20    // 16+4: frag banks (20*qr+qc) all distinct
#define BS_LD 136   // 128+8: frag banks (8*qc+qr) all distinct

struct SmemBuf {
    float As[2][128][AS_LD];
    float Bs[2][TBK][BS_LD];
};

__device__ __forceinline__ void tgemm_body(
    SmemBuf& sm,
    const float* __restrict__ A, const float* __restrict__ B,
    const float* __restrict__ bias, float* __restrict__ C,
    int M, int N, int K, int ldb, int ldc)
{
    const int tid  = threadIdx.x;
    const int row0 = blockIdx.y * 128;
    const int col0 = blockIdx.x * 128;
    if (row0 >= M || col0 >= N) return;
    const int wid  = tid >> 5;
    const int lane = tid & 31;
    const int warpM = (wid & 1) * 64;
    const int warpN = (wid >> 1) * 32;
    const int qr = lane >> 2;   // 0..7
    const int qc = lane & 3;    // 0..3

    // loader geometry
    const int aRow  = tid >> 2;          // 0..63 (+64)
    const int aCol4 = (tid & 3) << 2;
    const int bRow  = tid >> 5;          // 0..7 (+8)
    const int bCol4 = (tid & 31) << 2;
    const bool bValid = (col0 + bCol4 + 3) < N;

    float acc[4][4][4];
#pragma unroll
    for (int mt = 0; mt < 4; mt++)
#pragma unroll
        for (int nt = 0; nt < 4; nt++)
#pragma unroll
            for (int i = 0; i < 4; i++) acc[mt][nt][i] = 0.f;

    // prologue: load k-tile 0 into regs, store stage 0
    float4 ar[2], br[2];
#pragma unroll
    for (int it = 0; it < 2; it++) {
        ar[it] = *reinterpret_cast<const float4*>(
            A + (size_t)(row0 + aRow + it * 64) * K + aCol4);
        br[it] = bValid ? *reinterpret_cast<const float4*>(
                     B + (size_t)(bRow + it * 8) * ldb + col0 + bCol4)
                        : make_float4(0.f, 0.f, 0.f, 0.f);
    }
#pragma unroll
    for (int it = 0; it < 2; it++) {
        int r = aRow + it * 64;
        sm.As[0][r][aCol4 + 0] = f2tf32(ar[it].x);
        sm.As[0][r][aCol4 + 1] = f2tf32(ar[it].y);
        sm.As[0][r][aCol4 + 2] = f2tf32(ar[it].z);
        sm.As[0][r][aCol4 + 3] = f2tf32(ar[it].w);
        int rb = bRow + it * 8;
        sm.Bs[0][rb][bCol4 + 0] = f2tf32(br[it].x);
        sm.Bs[0][rb][bCol4 + 1] = f2tf32(br[it].y);
        sm.Bs[0][rb][bCol4 + 2] = f2tf32(br[it].z);
        sm.Bs[0][rb][bCol4 + 3] = f2tf32(br[it].w);
    }
    __syncthreads();

    int stage = 0;
    for (int k0 = 0; k0 < K; k0 += TBK) {
        const bool has_next = (k0 + TBK) < K;
        if (has_next) {
            int kn = k0 + TBK;
#pragma unroll
            for (int it = 0; it < 2; it++) {
                ar[it] = *reinterpret_cast<const float4*>(
                    A + (size_t)(row0 + aRow + it * 64) * K + kn + aCol4);
                br[it] = bValid ? *reinterpret_cast<const float4*>(
                             B + (size_t)(kn + bRow + it * 8) * ldb + col0 + bCol4)
                                : make_float4(0.f, 0.f, 0.f, 0.f);
            }
        }

        // compute on current stage
#pragma unroll
        for (int ks = 0; ks < 2; ks++) {
            const int kb = ks * 8;
            unsigned bfr[4][2];
#pragma unroll
            for (int nt = 0; nt < 4; nt++) {
                int bc = warpN + nt * 8 + qr;
                bfr[nt][0] = __float_as_uint(sm.Bs[stage][kb + qc][bc]);
                bfr[nt][1] = __float_as_uint(sm.Bs[stage][kb + qc + 4][bc]);
            }
#pragma unroll
            for (int mt = 0; mt < 4; mt++) {
                int arr = warpM + mt * 16 + qr;
                unsigned a0 = __float_as_uint(sm.As[stage][arr][kb + qc]);
                unsigned a1 = __float_as_uint(sm.As[stage][arr + 8][kb + qc]);
                unsigned a2 = __float_as_uint(sm.As[stage][arr][kb + qc + 4]);
                unsigned a3 = __float_as_uint(sm.As[stage][arr + 8][kb + qc + 4]);
#pragma unroll
                for (int nt = 0; nt < 4; nt++) {
                    asm volatile(
                        "mma.sync.aligned.m16n8k8.row.col.f32.tf32.tf32.f32 "
                        "{%0,%1,%2,%3}, {%4,%5,%6,%7}, {%8,%9}, {%0,%1,%2,%3};\n"
                        : "+f"(acc[mt][nt][0]), "+f"(acc[mt][nt][1]),
                          "+f"(acc[mt][nt][2]), "+f"(acc[mt][nt][3])
                        : "r"(a0), "r"(a1), "r"(a2), "r"(a3),
                          "r"(bfr[nt][0]), "r"(bfr[nt][1]));
                }
            }
        }

        if (has_next) {
            int ns = stage ^ 1;
#pragma unroll
            for (int it = 0; it < 2; it++) {
                int r = aRow + it * 64;
                sm.As[ns][r][aCol4 + 0] = f2tf32(ar[it].x);
                sm.As[ns][r][aCol4 + 1] = f2tf32(ar[it].y);
                sm.As[ns][r][aCol4 + 2] = f2tf32(ar[it].z);
                sm.As[ns][r][aCol4 + 3] = f2tf32(ar[it].w);
                int rb = bRow + it * 8;
                sm.Bs[ns][rb][bCol4 + 0] = f2tf32(br[it].x);
                sm.Bs[ns][rb][bCol4 + 1] = f2tf32(br[it].y);
                sm.Bs[ns][rb][bCol4 + 2] = f2tf32(br[it].z);
                sm.Bs[ns][rb][bCol4 + 3] = f2tf32(br[it].w);
            }
            __syncthreads();
            stage = ns;
        }
    }

    // epilogue: c0:(r,2qc) c1:(r,2qc+1) c2:(r+8,2qc) c3:(r+8,2qc+1)
#pragma unroll
    for (int nt = 0; nt < 4; nt++) {
        int col = col0 + warpN + nt * 8 + qc * 2;
        if (col >= N) continue;
        float b0 = bias ? bias[col] : 0.f;
        float b1 = bias ? bias[col + 1] : 0.f;
#pragma unroll
        for (int mt = 0; mt < 4; mt++) {
            int row = row0 + warpM + mt * 16 + qr;
            *reinterpret_cast<float2*>(C + (size_t)row * ldc + col) =
                make_float2(acc[mt][nt][0] + b0, acc[mt][nt][1] + b1);
            *reinterpret_cast<float2*>(C + (size_t)(row + 8) * ldc + col) =
                make_float2(acc[mt][nt][2] + b0, acc[mt][nt][3] + b1);
        }
    }
}

__global__ __launch_bounds__(256) void tgemm(
    const float* __restrict__ A, const float* __restrict__ B,
    const float* __restrict__ bias, float* __restrict__ C,
    int M, int N, int K, int ldb, int ldc)
{
    __shared__ SmemBuf sm;
    tgemm_body(sm, A, B, bias, C, M, N, K, ldb, ldc);
}

// ---------------- batched weight folds: one launch -------------------------
__global__ __launch_bounds__(256) void fold_all(
    const float* __restrict__ Wk,   const float* __restrict__ Wv,
    const float* __restrict__ Wo,   const float* __restrict__ Wout,
    const float* __restrict__ Wq,   const float* __restrict__ Woff,
    const float* __restrict__ Watt,
    float* __restrict__ Wkv, float* __restrict__ Wow, float* __restrict__ Wcomb)
{
    __shared__ SmemBuf sm;
    switch (blockIdx.z) {
    case 0: tgemm_body(sm, Wk, Wv,   nullptr, Wkv,       CH, CH, CH, CH, CH);  break;
    case 1: tgemm_body(sm, Wo, Wout, nullptr, Wow,       CH, CH, CH, CH, CH);  break;
    case 2: tgemm_body(sm, Wq, Woff, nullptr, Wcomb,     CH, 64, CH, 64, NLA); break;
    case 3: tgemm_body(sm, Wq, Watt, nullptr, Wcomb + 64, CH, 32, CH, 32, NLA); break;
    }
}

// --------------------------- bias folds ------------------------------------
__global__ void fold_bias(const float* __restrict__ bo,
                          const float* __restrict__ Wout,
                          const float* __restrict__ bout,
                          const float* __restrict__ boff,
                          const float* __restrict__ batt)
{
    int j = blockIdx.x * blockDim.x + threadIdx.x;
    if (j < CH) {
        float s = bout[j];
        for (int k = 0; k < CH; k++) s = fmaf(bo[k], Wout[k * CH + j], s);
        g_bow[j] = s;
    }
    if (j < 64)  g_bcomb[j] = boff[j];
    else if (j < NLA) g_bcomb[j] = batt[j - 64];
}

// ------------------- fused softmax + bilinear sampling ---------------------
// One warp per (b, pos, m). Lane l handles channels 2l, 2l+1.
__global__ __launch_bounds__(256) void deform_sample(
    const float* __restrict__ value,   // [ROWS, 512]
    const float* __restrict__ la,      // [ROWS, 96]: 64 off + 32 att
    float* __restrict__ outm)          // [ROWS, 512]
{
    int warp = (blockIdx.x * blockDim.x + threadIdx.x) >> 5;
    int lane = threadIdx.x & 31;
    if (warp >= ROWS * NHEAD) return;

    int m   = warp & 7;
    int bq  = warp >> 3;
    int b   = bq >> 12;
    int pos = bq & 4095;
    float col = (float)(pos & 63);
    float row = (float)(pos >> 6);

    const float* lo  = la + (size_t)bq * NLA + m * 8;
    const float* lat = la + (size_t)bq * NLA + 64 + m * 4;

    float l0 = lat[0], l1 = lat[1], l2 = lat[2], l3 = lat[3];
    float mx = fmaxf(fmaxf(l0, l1), fmaxf(l2, l3));
    float e0 = __expf(l0 - mx), e1 = __expf(l1 - mx),
          e2 = __expf(l2 - mx), e3 = __expf(l3 - mx);
    float inv = 1.f / (e0 + e1 + e2 + e3);
    float aw[4] = {e0 * inv, e1 * inv, e2 * inv, e3 * inv};

    const float* vbase = value + ((size_t)b * WH) * CH + m * DHEAD + 2 * lane;
    float accx = 0.f, accy = 0.f;

#pragma unroll
    for (int p = 0; p < NPTS; p++) {
        float x = col + lo[2 * p];
        float y = row + lo[2 * p + 1];
        float xf = floorf(x), yf = floorf(y);
        float wx1 = x - xf, wy1 = y - yf;
        int x0 = (int)xf, y0 = (int)yf;
        float a = aw[p];
#pragma unroll
        for (int dy = 0; dy < 2; dy++) {
#pragma unroll
            for (int dx = 0; dx < 2; dx++) {
                int xi = x0 + dx, yi = y0 + dy;
                if ((unsigned)xi < 64u && (unsigned)yi < 64u) {
                    float w = a * (dx ? wx1 : 1.f - wx1) * (dy ? wy1 : 1.f - wy1);
                    float2 v = *reinterpret_cast<const float2*>(
                        vbase + (size_t)(yi * 64 + xi) * CH);
                    accx = fmaf(w, v.x, accx);
                    accy = fmaf(w, v.y, accy);
                }
            }
        }
    }
    *reinterpret_cast<float2*>(outm + (size_t)bq * CH + m * DHEAD + 2 * lane) =
        make_float2(accx, accy);
}

// ------------------------------- launch ------------------------------------
extern "C" void kernel_launch(void* const* d_in, const int* in_sizes, int n_in,
                              void* d_out, int out_size)
{
    const float* x    = (const float*)d_in[0];
    const float* ctx  = (const float*)d_in[1];
    const float* Wq   = (const float*)d_in[4];
    const float* Wk   = (const float*)d_in[5];
    const float* Wv   = (const float*)d_in[6];
    const float* bv   = (const float*)d_in[7];
    const float* Woff = (const float*)d_in[8];
    const float* boff = (const float*)d_in[9];
    const float* Watt = (const float*)d_in[10];
    const float* batt = (const float*)d_in[11];
    const float* Wo   = (const float*)d_in[12];
    const float* bo   = (const float*)d_in[13];
    const float* Wout = (const float*)d_in[14];
    const float* bout = (const float*)d_in[15];
    float* out = (float*)d_out;

    static float *p_Wkv = nullptr, *p_Wow = nullptr, *p_Wcomb = nullptr,
                 *p_bcomb = nullptr, *p_bow = nullptr, *p_value = nullptr,
                 *p_la = nullptr, *p_mid = nullptr;
    if (!p_Wkv) {
        cudaGetSymbolAddress((void**)&p_Wkv, g_Wkv);
        cudaGetSymbolAddress((void**)&p_Wow, g_Wow);
        cudaGetSymbolAddress((void**)&p_Wcomb, g_Wcomb);
        cudaGetSymbolAddress((void**)&p_bcomb, g_bcomb);
        cudaGetSymbolAddress((void**)&p_bow, g_bow);
        cudaGetSymbolAddress((void**)&p_value, g_value);
        cudaGetSymbolAddress((void**)&p_la, g_la);
        cudaGetSymbolAddress((void**)&p_mid, g_mid);
    }

    dim3 blk(256);

    // all weight folds in one launch (grid.z = which fold)
    fold_all<<<dim3(4, 4, 4), blk>>>(Wk, Wv, Wo, Wout, Wq, Woff, Watt,
                                     p_Wkv, p_Wow, p_Wcomb);
    fold_bias<<<1, 512>>>(bo, Wout, bout, boff, batt);

    // main projections
    tgemm<<<dim3(4, 256), blk>>>(ctx, p_Wkv, bv, p_value, ROWS, CH, CH, CH, CH);
    tgemm<<<dim3(1, 256), blk>>>(x, p_Wcomb, p_bcomb, p_la, ROWS, NLA, CH, NLA, NLA);

    // fused softmax + deformable bilinear sampling
    int nwarps = ROWS * NHEAD;
    deform_sample<<<(nwarps * 32 + 255) / 256, blk>>>(p_value, p_la, p_mid);

    // output projection (folded Wo@Wout)
    tgemm<<<dim3(4, 256), blk>>>(p_mid, p_Wow, p_bow, out, ROWS, CH, CH, CH, CH);
}